// round 16
// baseline (speedup 1.0000x reference)
#include <cuda_runtime.h>
#include <cstdint>

#define HW 1024
#define PLANE (HW * HW)
#define BMAX 16

// Ping-pong scratch for the low-pass images (allocation-free rule).
static __device__ float g_lowA[BMAX * PLANE];
static __device__ float g_lowB[BMAX * PLANE];

__device__ __forceinline__ int refl(int i) {
    // jnp.pad 'symmetric': -1 -> 0, -2 -> 1, N -> N-1
    if (i < 0)   i = -1 - i;
    if (i >= HW) i = 2 * HW - 1 - i;
    return i;
}

__device__ __forceinline__ float4 rev4(const float4 v) {
    return make_float4(v.w, v.z, v.y, v.x);
}

// One starlet scale (R13-proven body, S=16 strips). Vertical dilated-by-D conv
// == plain 5-tap conv on each of D row-subsampled sub-images. Block = 256
// threads = one full 1024-float row. blockIdx.y = residue, blockIdx.x = strip
// of S sub-rows, blockIdx.z = batch.
//
// R=2 slabs: vertical results v0,v1 stay in registers across the barrier as
// the horizontal center tap; next slab's 2 LDG.128 issue before the barrier;
// double-buffered smem -> one __syncthreads per slab. Reflected 16-float
// x-halo makes the horizontal pass branch-free for all 256 threads.
template<int D, int SRC, int DST, bool STREAMRD>
__global__ __launch_bounds__(256, 4)
void starlet_stream(const float* __restrict__ ext_in,
                    const float* __restrict__ norms,
                    int scale,
                    float* __restrict__ coeff_out)
{
    constexpr int S = 16;                 // sub-rows per block (fine grain)
    constexpr int NSLAB = S / 2;
    constexpr int PAD = 16;               // halo floats per side (covers 2D<=16)
    constexpr int SMS = PAD + HW + PAD + 4;
    constexpr float W0 = 1.0f / 16.0f;
    constexpr float W1 = 1.0f / 4.0f;
    constexpr float W2 = 3.0f / 8.0f;

    __shared__ __align__(16) float sm[2][2][SMS];

    const int t     = threadIdx.x;        // float4 column 0..255
    const int resid = blockIdx.y;         // residue class
    const int s0    = blockIdx.x * S;     // first sub-row of strip
    const int b     = blockIdx.z;

    const float* src  = (SRC == 0) ? ext_in : (SRC == 1 ? g_lowA : g_lowB);
    const float* simg = src + (size_t)b * PLANE;
    float* lowdst = (DST == 1) ? g_lowA : (DST == 2 ? g_lowB : nullptr);
    if (DST != 0) lowdst += (size_t)b * PLANE;

    const int x4 = 4 * t;
    const int xb = PAD + x4;              // smem base index for this thread
    const float inv = 1.0f / norms[scale];
    const size_t step = (size_t)D * HW;   // float stride between sub-rows

    auto ld4 = [](const float* p) -> float4 {
        if constexpr (STREAMRD) return __ldcs(reinterpret_cast<const float4*>(p));
        else                    return *reinterpret_cast<const float4*>(p);
    };

    auto vcomb = [](const float4& a, const float4& bb, const float4& c,
                    const float4& d, const float4& e) -> float4 {
        float4 v;
        v.x = W0 * (a.x + e.x) + W1 * (bb.x + d.x) + W2 * c.x;
        v.y = W0 * (a.y + e.y) + W1 * (bb.y + d.y) + W2 * c.y;
        v.z = W0 * (a.z + e.z) + W1 * (bb.z + d.z) + W2 * c.z;
        v.w = W0 * (a.w + e.w) + W1 * (bb.w + d.w) + W2 * c.w;
        return v;
    };

    auto run = [&](auto&& ldnext) {
        float4 w0 = ldnext(), w1 = ldnext(), w2 = ldnext(), w3 = ldnext();
        float4 n0 = ldnext(), n1 = ldnext();

        float* cp = coeff_out + ((size_t)b * HW + (size_t)(resid + D * s0)) * HW + x4;
        float* lp = (DST != 0) ? lowdst + (size_t)(resid + D * s0) * HW + x4 : nullptr;

        #pragma unroll 4
        for (int slab = 0; slab < NSLAB; slab++) {
            const int buf = slab & 1;

            // ---- vertical 5-tap; results stay in regs as horizontal centers ----
            const float4 v0 = vcomb(w0, w1, w2, w3, n0);
            const float4 v1 = vcomb(w1, w2, w3, n0, n1);
            *reinterpret_cast<float4*>(&sm[buf][0][xb]) = v0;
            *reinterpret_cast<float4*>(&sm[buf][1][xb]) = v1;

            // reflected x-halo: ext col -1-k == col k ; ext col 1024+k == col 1023-k
            if (t < 4) {                                   // left halo f4 -(t+1)
                const int o = PAD - 4 * (t + 1);
                *reinterpret_cast<float4*>(&sm[buf][0][o]) = rev4(v0);
                *reinterpret_cast<float4*>(&sm[buf][1][o]) = rev4(v1);
            } else if (t >= 252) {                         // right halo f4 256+(255-t)
                const int o = PAD + HW + 4 * (255 - t);
                *reinterpret_cast<float4*>(&sm[buf][0][o]) = rev4(v0);
                *reinterpret_cast<float4*>(&sm[buf][1][o]) = rev4(v1);
            }

            // shift window (raw centers become new w0,w1)
            w0 = w2; w1 = w3; w2 = n0; w3 = n1;

            // prefetch next slab's rows (in flight across the barrier)
            if (slab + 1 < NSLAB) { n0 = ldnext(); n1 = ldnext(); }

            __syncthreads();

            // ---- horizontal 5-tap (dilated by D along x): uniform, branch-free ----
            #pragma unroll
            for (int r = 0; r < 2; r++) {
                const float* smrow = sm[buf][r];
                const float4 vc  = (r == 0) ? v0 : v1;
                const float4 raw = (r == 0) ? w0 : w1;
                float4 low;

                if constexpr (D >= 4) {
                    constexpr int G = D / 4;               // tap offset in f4 groups
                    const float4 a  = *reinterpret_cast<const float4*>(&smrow[xb - 8 * G]);
                    const float4 bb = *reinterpret_cast<const float4*>(&smrow[xb - 4 * G]);
                    const float4 d  = *reinterpret_cast<const float4*>(&smrow[xb + 4 * G]);
                    const float4 e  = *reinterpret_cast<const float4*>(&smrow[xb + 8 * G]);
                    low = vcomb(a, bb, vc, d, e);
                } else {
                    float fl[12];
                    *reinterpret_cast<float4*>(&fl[0]) = *reinterpret_cast<const float4*>(&smrow[xb - 4]);
                    fl[4] = vc.x; fl[5] = vc.y; fl[6] = vc.z; fl[7] = vc.w;
                    *reinterpret_cast<float4*>(&fl[8]) = *reinterpret_cast<const float4*>(&smrow[xb + 4]);
                    float lo[4];
                    #pragma unroll
                    for (int j = 0; j < 4; j++) {
                        lo[j] = W0 * (fl[4 + j - 2 * D] + fl[4 + j + 2 * D])
                              + W1 * (fl[4 + j - D]     + fl[4 + j + D])
                              + W2 *  fl[4 + j];
                    }
                    low.x = lo[0]; low.y = lo[1]; low.z = lo[2]; low.w = lo[3];
                }

                float4 cf;
                cf.x = (raw.x - low.x) * inv;
                cf.y = (raw.y - low.y) * inv;
                cf.z = (raw.z - low.z) * inv;
                cf.w = (raw.w - low.w) * inv;

                __stcs(reinterpret_cast<float4*>(cp), cf);   // streaming store
                cp += step;
                if (DST != 0) {
                    *reinterpret_cast<float4*>(lp) = low;    // keep in L2
                    lp += step;
                }
            }
            // double-buffered smem: no trailing barrier
        }
    };

    const int HWsub = HW / D;   // sub-image height
    if (s0 >= 2 && s0 + S + 2 <= HWsub) {
        // interior strip: pure incremental pointer, no reflection possible
        const float* p = simg + (size_t)(resid + D * (s0 - 2)) * HW + x4;
        run([&]() -> float4 {
            const float4 v = ld4(p);
            p += step;
            return v;
        });
    } else {
        // boundary strip: reflected row indices
        int s = s0 - 2;
        run([&]() -> float4 {
            const int f = refl(resid + D * s);
            s++;
            return ld4(simg + (size_t)f * HW + x4);
        });
    }
}

extern "C" void kernel_launch(void* const* d_in, const int* in_sizes, int n_in,
                              void* d_out, int out_size)
{
    int img_idx = 0, nrm_idx = 1;
    if (n_in >= 2 && in_sizes[0] == 4) { img_idx = 1; nrm_idx = 0; }

    const float* image = (const float*)d_in[img_idx];
    const float* norms = (const float*)d_in[nrm_idx];
    float* out = (float*)d_out;

    int B = in_sizes[img_idx] / PLANE;
    if (B < 1) B = 1;
    if (B > BMAX) B = BMAX;
    const size_t plane_all = (size_t)B * PLANE;

    const dim3 block(256);
    // grid: x = strips of 16 sub-rows, y = D residues, z = batch (1024 blocks/scale)
    const dim3 g1(HW / (1 * 16), 1, B);
    const dim3 g2(HW / (2 * 16), 2, B);
    const dim3 g4(HW / (4 * 16), 4, B);
    const dim3 g8(HW / (8 * 16), 8, B);

    // scale 0: image (streaming read: read-once) -> lowA
    starlet_stream<1, 0, 1, true ><<<g1, block>>>(image, norms, 0, out + 0 * plane_all);
    // scale 1: lowA -> lowB (lowA stays cached: default read)
    starlet_stream<2, 1, 2, false><<<g2, block>>>(image, norms, 1, out + 1 * plane_all);
    // scale 2: lowB -> lowA
    starlet_stream<4, 2, 1, false><<<g4, block>>>(image, norms, 2, out + 2 * plane_all);
    // scale 3: lowA -> (none); last use of lowA -> streaming read
    starlet_stream<8, 1, 0, true ><<<g8, block>>>(image, norms, 3, out + 3 * plane_all);
}

// round 17
// speedup vs baseline: 1.4304x; 1.4304x over previous
#include <cuda_runtime.h>
#include <cstdint>

#define HW 1024
#define PLANE (HW * HW)
#define BMAX 16

// Ping-pong scratch for the low-pass images (allocation-free rule).
static __device__ float g_lowA[BMAX * PLANE];
static __device__ float g_lowB[BMAX * PLANE];

__device__ __forceinline__ int refl(int i) {
    // jnp.pad 'symmetric': -1 -> 0, -2 -> 1, N -> N-1
    if (i < 0)   i = -1 - i;
    if (i >= HW) i = 2 * HW - 1 - i;
    return i;
}

__device__ __forceinline__ float4 rev4(const float4 v) {
    return make_float4(v.w, v.z, v.y, v.x);
}

// PDL: dependent kernels wait here before their first read of g_low*.
__device__ __forceinline__ void pdl_wait() {
    asm volatile("griddepcontrol.wait;" ::: "memory");
}
__device__ __forceinline__ void pdl_trigger() {
    asm volatile("griddepcontrol.launch_dependents;");
}

// One starlet scale (R13-proven body, S=32). Vertical dilated-by-D conv ==
// plain 5-tap conv on each of D row-subsampled sub-images. Block = 256
// threads = one full 1024-float row. blockIdx.y = residue, blockIdx.x =
// strip of S sub-rows, blockIdx.z = batch.
//
// R=2 slabs: vertical results v0,v1 stay in registers across the barrier as
// the horizontal center tap; next slab's 2 LDG.128 issue before the barrier;
// double-buffered smem -> one __syncthreads per slab. Reflected 16-float
// x-halo makes the horizontal pass branch-free for all 256 threads.
template<int D, int SRC, int DST, bool STREAMRD>
__global__ __launch_bounds__(256, 4)
void starlet_stream(const float* __restrict__ ext_in,
                    const float* __restrict__ norms,
                    int scale,
                    float* __restrict__ coeff_out)
{
    constexpr int S = 32;                 // sub-rows per block
    constexpr int NSLAB = S / 2;
    constexpr int PAD = 16;               // halo floats per side (covers 2D<=16)
    constexpr int SMS = PAD + HW + PAD + 4;
    constexpr float W0 = 1.0f / 16.0f;
    constexpr float W1 = 1.0f / 4.0f;
    constexpr float W2 = 3.0f / 8.0f;

    __shared__ __align__(16) float sm[2][2][SMS];

    const int t     = threadIdx.x;        // float4 column 0..255
    const int resid = blockIdx.y;         // residue class
    const int s0    = blockIdx.x * S;     // first sub-row of strip
    const int b     = blockIdx.z;

    const float* src  = (SRC == 0) ? ext_in : (SRC == 1 ? g_lowA : g_lowB);
    const float* simg = src + (size_t)b * PLANE;
    float* lowdst = (DST == 1) ? g_lowA : (DST == 2 ? g_lowB : nullptr);
    if (DST != 0) lowdst += (size_t)b * PLANE;

    const int x4 = 4 * t;
    const int xb = PAD + x4;              // smem base index for this thread
    const float inv = 1.0f / norms[scale];
    const size_t step = (size_t)D * HW;   // float stride between sub-rows

    // Dependent kernels (reading g_low*) wait for the predecessor grid.
    if constexpr (SRC != 0) pdl_wait();

    auto ld4 = [](const float* p) -> float4 {
        if constexpr (STREAMRD) return __ldcs(reinterpret_cast<const float4*>(p));
        else                    return *reinterpret_cast<const float4*>(p);
    };

    auto vcomb = [](const float4& a, const float4& bb, const float4& c,
                    const float4& d, const float4& e) -> float4 {
        float4 v;
        v.x = W0 * (a.x + e.x) + W1 * (bb.x + d.x) + W2 * c.x;
        v.y = W0 * (a.y + e.y) + W1 * (bb.y + d.y) + W2 * c.y;
        v.z = W0 * (a.z + e.z) + W1 * (bb.z + d.z) + W2 * c.z;
        v.w = W0 * (a.w + e.w) + W1 * (bb.w + d.w) + W2 * c.w;
        return v;
    };

    auto run = [&](auto&& ldnext) {
        float4 w0 = ldnext(), w1 = ldnext(), w2 = ldnext(), w3 = ldnext();
        float4 n0 = ldnext(), n1 = ldnext();

        float* cp = coeff_out + ((size_t)b * HW + (size_t)(resid + D * s0)) * HW + x4;
        float* lp = (DST != 0) ? lowdst + (size_t)(resid + D * s0) * HW + x4 : nullptr;

        #pragma unroll 4
        for (int slab = 0; slab < NSLAB; slab++) {
            const int buf = slab & 1;

            // ---- vertical 5-tap; results stay in regs as horizontal centers ----
            const float4 v0 = vcomb(w0, w1, w2, w3, n0);
            const float4 v1 = vcomb(w1, w2, w3, n0, n1);
            *reinterpret_cast<float4*>(&sm[buf][0][xb]) = v0;
            *reinterpret_cast<float4*>(&sm[buf][1][xb]) = v1;

            // reflected x-halo: ext col -1-k == col k ; ext col 1024+k == col 1023-k
            if (t < 4) {                                   // left halo f4 -(t+1)
                const int o = PAD - 4 * (t + 1);
                *reinterpret_cast<float4*>(&sm[buf][0][o]) = rev4(v0);
                *reinterpret_cast<float4*>(&sm[buf][1][o]) = rev4(v1);
            } else if (t >= 252) {                         // right halo f4 256+(255-t)
                const int o = PAD + HW + 4 * (255 - t);
                *reinterpret_cast<float4*>(&sm[buf][0][o]) = rev4(v0);
                *reinterpret_cast<float4*>(&sm[buf][1][o]) = rev4(v1);
            }

            // shift window (raw centers become new w0,w1)
            w0 = w2; w1 = w3; w2 = n0; w3 = n1;

            // prefetch next slab's rows (in flight across the barrier)
            if (slab + 1 < NSLAB) { n0 = ldnext(); n1 = ldnext(); }

            __syncthreads();

            // ---- horizontal 5-tap (dilated by D along x): uniform, branch-free ----
            #pragma unroll
            for (int r = 0; r < 2; r++) {
                const float* smrow = sm[buf][r];
                const float4 vc  = (r == 0) ? v0 : v1;
                const float4 raw = (r == 0) ? w0 : w1;
                float4 low;

                if constexpr (D >= 4) {
                    constexpr int G = D / 4;               // tap offset in f4 groups
                    const float4 a  = *reinterpret_cast<const float4*>(&smrow[xb - 8 * G]);
                    const float4 bb = *reinterpret_cast<const float4*>(&smrow[xb - 4 * G]);
                    const float4 d  = *reinterpret_cast<const float4*>(&smrow[xb + 4 * G]);
                    const float4 e  = *reinterpret_cast<const float4*>(&smrow[xb + 8 * G]);
                    low = vcomb(a, bb, vc, d, e);
                } else {
                    float fl[12];
                    *reinterpret_cast<float4*>(&fl[0]) = *reinterpret_cast<const float4*>(&smrow[xb - 4]);
                    fl[4] = vc.x; fl[5] = vc.y; fl[6] = vc.z; fl[7] = vc.w;
                    *reinterpret_cast<float4*>(&fl[8]) = *reinterpret_cast<const float4*>(&smrow[xb + 4]);
                    float lo[4];
                    #pragma unroll
                    for (int j = 0; j < 4; j++) {
                        lo[j] = W0 * (fl[4 + j - 2 * D] + fl[4 + j + 2 * D])
                              + W1 * (fl[4 + j - D]     + fl[4 + j + D])
                              + W2 *  fl[4 + j];
                    }
                    low.x = lo[0]; low.y = lo[1]; low.z = lo[2]; low.w = lo[3];
                }

                float4 cf;
                cf.x = (raw.x - low.x) * inv;
                cf.y = (raw.y - low.y) * inv;
                cf.z = (raw.z - low.z) * inv;
                cf.w = (raw.w - low.w) * inv;

                __stcs(reinterpret_cast<float4*>(cp), cf);   // streaming store
                cp += step;
                if (DST != 0) {
                    *reinterpret_cast<float4*>(lp) = low;    // keep in L2
                    lp += step;
                }
            }
            // double-buffered smem: no trailing barrier
        }
    };

    const int HWsub = HW / D;   // sub-image height
    if (s0 >= 2 && s0 + S + 2 <= HWsub) {
        // interior strip: pure incremental pointer, no reflection possible
        const float* p = simg + (size_t)(resid + D * (s0 - 2)) * HW + x4;
        run([&]() -> float4 {
            const float4 v = ld4(p);
            p += step;
            return v;
        });
    } else {
        // boundary strip: reflected row indices
        int s = s0 - 2;
        run([&]() -> float4 {
            const int f = refl(resid + D * s);
            s++;
            return ld4(simg + (size_t)f * HW + x4);
        });
    }

    // Signal dependents (low writes of this CTA are done).
    pdl_trigger();
}

template<typename K>
static void launch_pdl(K kernel, dim3 grid, dim3 block, bool dependent,
                       const float* image, const float* norms, int scale,
                       float* coeff)
{
    cudaLaunchConfig_t cfg = {};
    cfg.gridDim = grid;
    cfg.blockDim = block;
    cfg.dynamicSmemBytes = 0;
    cfg.stream = 0;
    cudaLaunchAttribute at[1];
    cfg.numAttrs = 0;
    if (dependent) {
        at[0].id = cudaLaunchAttributeProgrammaticStreamSerialization;
        at[0].val.programmaticStreamSerializationAllowed = 1;
        cfg.attrs = at;
        cfg.numAttrs = 1;
    }
    cudaLaunchKernelEx(&cfg, kernel, image, norms, scale, coeff);
}

extern "C" void kernel_launch(void* const* d_in, const int* in_sizes, int n_in,
                              void* d_out, int out_size)
{
    int img_idx = 0, nrm_idx = 1;
    if (n_in >= 2 && in_sizes[0] == 4) { img_idx = 1; nrm_idx = 0; }

    const float* image = (const float*)d_in[img_idx];
    const float* norms = (const float*)d_in[nrm_idx];
    float* out = (float*)d_out;

    int B = in_sizes[img_idx] / PLANE;
    if (B < 1) B = 1;
    if (B > BMAX) B = BMAX;
    const size_t plane_all = (size_t)B * PLANE;

    const dim3 block(256);
    // grid: x = strips of 32 sub-rows, y = D residues, z = batch (512 blocks/scale)
    const dim3 g1(HW / (1 * 32), 1, B);
    const dim3 g2(HW / (2 * 32), 2, B);
    const dim3 g4(HW / (4 * 32), 4, B);
    const dim3 g8(HW / (8 * 32), 8, B);

    // scale 0: image (streaming read) -> lowA          [no PDL wait]
    launch_pdl(starlet_stream<1, 0, 1, true >, g1, block, false,
               image, norms, 0, out + 0 * plane_all);
    // scale 1: lowA -> lowB                            [PDL dependent]
    launch_pdl(starlet_stream<2, 1, 2, false>, g2, block, true,
               image, norms, 1, out + 1 * plane_all);
    // scale 2: lowB -> lowA                            [PDL dependent]
    launch_pdl(starlet_stream<4, 2, 1, false>, g4, block, true,
               image, norms, 2, out + 2 * plane_all);
    // scale 3: lowA -> (none), streaming read          [PDL dependent]
    launch_pdl(starlet_stream<8, 1, 0, true >, g8, block, true,
               image, norms, 3, out + 3 * plane_all);
}